// round 15
// baseline (speedup 1.0000x reference)
#include <cuda_runtime.h>
#include <cuda_fp16.h>
#include <cstdint>

#define NN 50000
#define EE 400000
#define FF 256
#define HH 512
#define CC 3
#define NPAD 50048                        // 391 * 128
#define CHA64 ((size_t)NPAD * 128)        // A k64-chunk stride (bytes)
#define WCH64 ((size_t)512 * 128)         // W k64-chunk stride (bytes)
#define WSLOT ((size_t)8 * 512 * 128)     // W layer slot stride (bytes)

// ---------------- device scratch ----------------
__device__ __half g_Xin[(size_t)NN * FF];                // fp16 copy of input x
__device__ __half g_Xa[(size_t)NPAD * HH];               // ping-pong activations
__device__ __half g_Xb[(size_t)NPAD * HH];
__device__ unsigned char g_A[(size_t)8 * NPAD * 128];    // fp16 A, blocked+swizzled
__device__ unsigned char g_W[(size_t)13 * 8 * 512 * 128]; // fp16 W, blocked+swizzled
__device__ float g_S[(size_t)NN * CC];
__device__ float g_dinv[NN];
__device__ float g_coef[EE + NN];
__device__ int   g_col[EE + NN];
__device__ int   g_srcA[EE];
__device__ int   g_dstA[EE];
__device__ int   g_cnt[NN];
__device__ int   g_fill[NN];
__device__ int   g_rowptr[NN + 1];
__device__ unsigned g_is32;

// ---------------- preprocessing ----------------
__global__ void detect_kernel(const uint4* __restrict__ w) {
    unsigned local = 0;
    for (int i = blockIdx.x * blockDim.x + threadIdx.x; i < 200000;
         i += gridDim.x * blockDim.x) {
        uint4 v = w[i];
        local |= v.y | v.w;
    }
    #pragma unroll
    for (int off = 16; off; off >>= 1)
        local |= __shfl_xor_sync(0xffffffffu, local, off);
    if ((threadIdx.x & 31) == 0 && local) atomicOr(&g_is32, 1u);
}

__global__ void convert_count_kernel(const void* __restrict__ ei) {
    int e = blockIdx.x * blockDim.x + threadIdx.x;
    if (e >= EE) return;
    int s, d;
    if (g_is32) {
        const int* p = (const int*)ei;
        s = p[e]; d = p[EE + e];
    } else {
        const long long* p = (const long long*)ei;
        s = (int)p[e]; d = (int)p[EE + e];
    }
    g_srcA[e] = s; g_dstA[e] = d;
    atomicAdd(&g_cnt[d], 1);
}

__global__ void scan_kernel() {
    __shared__ int s[1024];
    const int T = 1024;
    int tid = threadIdx.x;
    int chunk = (NN + T - 1) / T;
    int beg = tid * chunk;
    int end = min(beg + chunk, NN);
    int sum = 0;
    for (int i = beg; i < end; i++) sum += g_cnt[i] + 1;
    s[tid] = sum;
    __syncthreads();
    for (int off = 1; off < T; off <<= 1) {
        int v = (tid >= off) ? s[tid - off] : 0;
        __syncthreads();
        s[tid] += v;
        __syncthreads();
    }
    int run = (tid > 0) ? s[tid - 1] : 0;
    for (int i = beg; i < end; i++) {
        int c = g_cnt[i];
        float di = rsqrtf((float)c + 1.0f);
        g_rowptr[i] = run;
        g_dinv[i] = di;
        g_col[run + c] = i;
        g_coef[run + c] = di * di;
        run += c + 1;
    }
    if (tid == T - 1) g_rowptr[NN] = run;
}

__global__ void fill_kernel() {
    int e = blockIdx.x * blockDim.x + threadIdx.x;
    if (e >= EE) return;
    int d = g_dstA[e], s = g_srcA[e];
    int pos = g_rowptr[d] + atomicAdd(&g_fill[d], 1);
    g_col[pos]  = s;
    g_coef[pos] = g_dinv[s] * g_dinv[d];
}

// ---------------- weight: fp16, blocked [L][kc64][n][128B], swizzled -------
__global__ void wsplit_kernel(const float* __restrict__ W0,
                              const float* __restrict__ Wr) {
    int L = blockIdx.y;
    int n = blockIdx.x;
    int K = (L == 0) ? FF : HH;
    const float* W = (L == 0) ? W0 : (Wr + (size_t)(L - 1) * HH * HH);
    unsigned char* slot = g_W + (size_t)L * WSLOT;
    int t = threadIdx.x;
    if (t >= (K >> 3)) return;
    int kc = t >> 3, u = t & 7, k0 = t * 8;
    unsigned w[4];
    #pragma unroll
    for (int p = 0; p < 4; p++) {
        unsigned lo = (unsigned)__half_as_ushort(
            __float2half_rn(W[(size_t)(k0 + 2 * p) * HH + n]));
        unsigned hi = (unsigned)__half_as_ushort(
            __float2half_rn(W[(size_t)(k0 + 2 * p + 1) * HH + n]));
        w[p] = lo | (hi << 16);
    }
    unsigned char* base = slot + (size_t)kc * WCH64 + (size_t)n * 128;
    uint32_t phys = ((uint32_t)(u ^ (n & 7))) << 4;
    *(uint4*)(base + phys) = make_uint4(w[0], w[1], w[2], w[3]);
}

// ---------------- fp32 -> fp16 convert (layer-0 input x) ----------------
__global__ void xcvt_kernel(const float* __restrict__ X, __half* __restrict__ Y) {
    size_t i = (size_t)blockIdx.x * blockDim.x + threadIdx.x;   // 8 floats each
    if (i >= (size_t)NN * FF / 8) return;
    const float4* src = (const float4*)X + 2 * i;
    float4 a = src[0], b = src[1];
    __half2 p0 = __floats2half2_rn(a.x, a.y);
    __half2 p1 = __floats2half2_rn(a.z, a.w);
    __half2 p2 = __floats2half2_rn(b.x, b.y);
    __half2 p3 = __floats2half2_rn(b.z, b.w);
    uint4 o;
    o.x = *(unsigned*)&p0; o.y = *(unsigned*)&p1;
    o.z = *(unsigned*)&p2; o.w = *(unsigned*)&p3;
    ((uint4*)Y)[i] = o;
}

// ---------------- aggregation helpers ----------------
__device__ __forceinline__ void agg_pack_store(unsigned char* __restrict__ gA,
                                               int node, int kc, int u,
                                               const float* acc) {
    uint4 ph;
    __half2 p0 = __floats2half2_rn(acc[0], acc[1]);
    __half2 p1 = __floats2half2_rn(acc[2], acc[3]);
    __half2 p2 = __floats2half2_rn(acc[4], acc[5]);
    __half2 p3 = __floats2half2_rn(acc[6], acc[7]);
    ph.x = *(unsigned*)&p0; ph.y = *(unsigned*)&p1;
    ph.z = *(unsigned*)&p2; ph.w = *(unsigned*)&p3;
    unsigned char* base = gA + (size_t)kc * CHA64 + (size_t)node * 128;
    uint32_t phys = ((uint32_t)(u ^ (node & 7))) << 4;
    *(uint4*)(base + phys) = ph;
}

#define AGG_ACCUM(v, cf)                                                      \
    do {                                                                      \
        float2 f0_ = __half22float2(*(__half2*)&(v).x);                       \
        float2 f1_ = __half22float2(*(__half2*)&(v).y);                       \
        float2 f2_ = __half22float2(*(__half2*)&(v).z);                       \
        float2 f3_ = __half22float2(*(__half2*)&(v).w);                       \
        acc[0] += (cf) * f0_.x; acc[1] += (cf) * f0_.y;                       \
        acc[2] += (cf) * f1_.x; acc[3] += (cf) * f1_.y;                       \
        acc[4] += (cf) * f2_.x; acc[5] += (cf) * f2_.y;                       \
        acc[6] += (cf) * f3_.x; acc[7] += (cf) * f3_.y;                       \
    } while (0)

// mid-layer agg quarter (K=512): 1 node per 64-thread block
__global__ void agg16_q_kernel(const __half* __restrict__ X,
                               unsigned char* __restrict__ gA, int nodeOff) {
    int node = nodeOff + blockIdx.x;
    int t = threadIdx.x;
    const uint4* Xv = (const uint4*)X;
    float acc[8];
    #pragma unroll
    for (int i = 0; i < 8; i++) acc[i] = 0.f;
    int beg = g_rowptr[node], end = g_rowptr[node + 1];
    int e = beg;
    for (; e + 1 < end; e += 2) {
        int s0 = g_col[e], s1 = g_col[e + 1];
        float c0 = g_coef[e], c1 = g_coef[e + 1];
        uint4 v0 = Xv[(size_t)s0 * 64 + t];
        uint4 v1 = Xv[(size_t)s1 * 64 + t];
        AGG_ACCUM(v0, c0);
        AGG_ACCUM(v1, c1);
    }
    if (e < end) {
        uint4 v0 = Xv[(size_t)g_col[e] * 64 + t];
        AGG_ACCUM(v0, g_coef[e]);
    }
    agg_pack_store(gA, node, t >> 3, t & 7, acc);
}

// layer-0 agg quarter (K=256): 2 nodes per 64-thread block
__global__ void agg16_l0q_kernel(const __half* __restrict__ X,
                                 unsigned char* __restrict__ gA,
                                 int nodeOff, int nodeCnt) {
    int loc = blockIdx.x * 2 + (threadIdx.x >> 5);
    if (loc >= nodeCnt) return;
    int node = nodeOff + loc;
    int t = threadIdx.x & 31;
    const uint4* Xv = (const uint4*)X;
    float acc[8];
    #pragma unroll
    for (int i = 0; i < 8; i++) acc[i] = 0.f;
    int beg = g_rowptr[node], end = g_rowptr[node + 1];
    for (int e = beg; e < end; e++) {
        uint4 v0 = Xv[(size_t)g_col[e] * 32 + t];
        AGG_ACCUM(v0, g_coef[e]);
    }
    agg_pack_store(gA, node, t >> 3, t & 7, acc);
}

// ---------------- HMMA fp16 GEMM, 128x256 tile, TMA, 3-stage ----------------
#define STG_B   49152
#define SMEM_REQ (1024 + 128 + 3 * STG_B)

#define MMA_F16(cc, A0, A1, A2, A3, B0, B1)                                   \
    asm volatile(                                                             \
        "mma.sync.aligned.m16n8k16.row.col.f32.f16.f16.f32 "                  \
        "{%0,%1,%2,%3}, {%4,%5,%6,%7}, {%8,%9}, {%0,%1,%2,%3};"               \
        : "+f"(cc[0]), "+f"(cc[1]), "+f"(cc[2]), "+f"(cc[3])                  \
        : "r"(A0), "r"(A1), "r"(A2), "r"(A3), "r"(B0), "r"(B1))

#define LDSM4(r0, r1, r2, r3, addr)                                           \
    asm volatile("ldmatrix.sync.aligned.m8n8.x4.shared.b16 {%0,%1,%2,%3}, [%4];" \
        : "=r"(r0), "=r"(r1), "=r"(r2), "=r"(r3) : "r"(addr))

__device__ __forceinline__ void mbar_wait(uint32_t mb, uint32_t parity) {
    uint32_t done;
    asm volatile("{\n\t.reg .pred p;\n\t"
                 "mbarrier.try_wait.parity.shared.b64 p, [%1], %2;\n\t"
                 "selp.b32 %0, 1, 0, p;\n\t}"
                 : "=r"(done) : "r"(mb), "r"(parity) : "memory");
    if (!done) {
        asm volatile("{\n\t.reg .pred P1;\n\t"
                     "WL_%=:\n\t"
                     "mbarrier.try_wait.parity.shared.b64 P1, [%0], %1;\n\t"
                     "@P1 bra.uni WD_%=;\n\t"
                     "bra.uni WL_%=;\n\t"
                     "WD_%=:\n\t}" :: "r"(mb), "r"(parity) : "memory");
    }
}

template <int OUT16>
__global__ void __launch_bounds__(256, 1) gemm_mma_kernel(
    const unsigned char* __restrict__ gA,
    const unsigned char* __restrict__ gW,
    const float* __restrict__ bias, void* __restrict__ XoutV,
    int M, int nTiles, int kshift, int nOff, int mTileOff) {
    extern __shared__ char smb[];
    uint32_t sraw;
    asm("{ .reg .u64 t; cvta.to.shared.u64 t, %1; cvt.u32.u64 %0, t; }"
        : "=r"(sraw) : "l"(smb));
    const uint32_t sb = (sraw + 1023) & ~1023u;
    const uint32_t bufBase = sb + 128;

    const int tid = threadIdx.x;
    const int lane = tid & 31, wid = tid >> 5;
    const int g = lane >> 2, t4 = lane & 3;
    const int warpM = wid & 1, warpN = wid >> 1;   // 2M x 4N, warp tile 64x64
    const int kmask = (1 << kshift) - 1;
    const int myTiles = (nTiles - blockIdx.x + gridDim.x - 1) / gridDim.x;
    const int totalSlots = myTiles << kshift;

    const int rx = lane & 7;
    const int aLRow = (lane & 7) + ((lane >> 3) & 1) * 8;
    const int colA = (lane >> 4) & 1;
    const int bLRow = (lane & 7) + ((lane >> 4) & 1) * 8;
    const int colB = (lane >> 3) & 1;
    const uint32_t aRowOff = (uint32_t)(warpM * 64 + aLRow) * 128;
    const uint32_t bRowOff = 16384u + (uint32_t)(warpN * 64 + bLRow) * 128;
    uint32_t pA[4], pB[4];
    #pragma unroll
    for (int j = 0; j < 4; j++) {
        pA[j] = (uint32_t)(((2 * j + colA) ^ rx) << 4);
        pB[j] = (uint32_t)(((2 * j + colB) ^ rx) << 4);
    }

    float acc[4][8][4];
    #pragma unroll
    for (int i = 0; i < 4; i++)
        #pragma unroll
        for (int j = 0; j < 8; j++)
            #pragma unroll
            for (int v = 0; v < 4; v++) acc[i][j][v] = 0.f;

    #define DECODE(s, cc, mB) do {                                             \
        int tI_ = (s) >> kshift;                                               \
        int tile_ = mTileOff + blockIdx.x + tI_ * gridDim.x;                   \
        cc = (s) & kmask;                                                      \
        mB = tile_ << 7;                                                       \
    } while (0)

    #define FILL(stage, cc, mB) do {                                           \
        uint32_t mb_ = sb + (stage) * 8;                                       \
        asm volatile("mbarrier.arrive.expect_tx.shared.b64 _, [%0], %1;"       \
            :: "r"(mb_), "r"(49152u) : "memory");                              \
        uint32_t d_ = bufBase + (stage) * STG_B;                               \
        asm volatile(                                                          \
            "cp.async.bulk.shared::cta.global.mbarrier::complete_tx::bytes "   \
            "[%0], [%1], %2, [%3];"                                            \
            :: "r"(d_), "l"(gA + (size_t)(cc) * CHA64 + (size_t)(mB) * 128),   \
               "r"(16384u), "r"(mb_) : "memory");                              \
        asm volatile(                                                          \
            "cp.async.bulk.shared::cta.global.mbarrier::complete_tx::bytes "   \
            "[%0], [%1], %2, [%3];"                                            \
            :: "r"(d_ + 16384u),                                               \
               "l"(gW + (size_t)(cc) * WCH64 + (size_t)(nOff) * 128),          \
               "r"(32768u), "r"(mb_) : "memory");                              \
    } while (0)

    if (tid == 0) {
        asm volatile("mbarrier.init.shared.b64 [%0], 1;" :: "r"(sb) : "memory");
        asm volatile("mbarrier.init.shared.b64 [%0], 1;" :: "r"(sb + 8) : "memory");
        asm volatile("mbarrier.init.shared.b64 [%0], 1;" :: "r"(sb + 16) : "memory");
    }
    __syncthreads();
    if (tid == 0) {
        int c0, m0; DECODE(0, c0, m0); FILL(0, c0, m0);
        if (totalSlots > 1) { int c1, m1; DECODE(1, c1, m1); FILL(1, c1, m1); }
    }

    int ph[3] = {0, 0, 0};
    int stage = 0;
    for (int s = 0; s < totalSlots; s++) {
        mbar_wait(sb + stage * 8, ph[stage]);
        ph[stage] ^= 1;

        if (tid == 0 && s + 2 < totalSlots) {
            int cN, mN;
            DECODE(s + 2, cN, mN);
            int nst = stage + 2; if (nst >= 3) nst -= 3;
            FILL(nst, cN, mN);
        }

        const uint32_t stA = bufBase + stage * STG_B;
        #pragma unroll
        for (int j = 0; j < 4; j++) {                  // kk16 within k64
            uint32_t bh[8][2];
            #pragma unroll
            for (int jp = 0; jp < 4; jp++) {
                uint32_t ba = stA + bRowOff + jp * 2048u + pB[j];
                LDSM4(bh[2 * jp][0], bh[2 * jp][1],
                      bh[2 * jp + 1][0], bh[2 * jp + 1][1], ba);
            }
            #pragma unroll
            for (int i = 0; i < 4; i++) {
                uint32_t aa = stA + aRowOff + i * 2048u + pA[j];
                uint32_t a0, a1, a2, a3;
                LDSM4(a0, a1, a2, a3, aa);
                #pragma unroll
                for (int jn = 0; jn < 8; jn++)
                    MMA_F16(acc[i][jn], a0, a1, a2, a3, bh[jn][0], bh[jn][1]);
            }
        }

        if ((s & kmask) == kmask) {
            int cE, mB;
            DECODE(s, cE, mB);
            #pragma unroll
            for (int j = 0; j < 8; j++) {
                int col = nOff + warpN * 64 + j * 8 + 2 * t4;
                float bv0 = __ldg(&bias[col]), bv1 = __ldg(&bias[col + 1]);
                #pragma unroll
                for (int i = 0; i < 4; i++) {
                    int r0 = mB + warpM * 64 + i * 16 + g;
                    int r1 = r0 + 8;
                    if (OUT16) {
                        __half* Xout = (__half*)XoutV;
                        if (r0 < M) {
                            __half2 v0 = __floats2half2_rn(
                                fmaxf(acc[i][j][0] + bv0, 0.f),
                                fmaxf(acc[i][j][1] + bv1, 0.f));
                            *(__half2*)(Xout + (size_t)r0 * HH + col) = v0;
                        }
                        if (r1 < M) {
                            __half2 v1 = __floats2half2_rn(
                                fmaxf(acc[i][j][2] + bv0, 0.f),
                                fmaxf(acc[i][j][3] + bv1, 0.f));
                            *(__half2*)(Xout + (size_t)r1 * HH + col) = v1;
                        }
                    } else {
                        float* Xout = (float*)XoutV;
                        if (r0 < M) {
                            float2 v0 = make_float2(fmaxf(acc[i][j][0] + bv0, 0.f),
                                                    fmaxf(acc[i][j][1] + bv1, 0.f));
                            *(float2*)(Xout + (size_t)r0 * HH + col) = v0;
                        }
                        if (r1 < M) {
                            float2 v1 = make_float2(fmaxf(acc[i][j][2] + bv0, 0.f),
                                                    fmaxf(acc[i][j][3] + bv1, 0.f));
                            *(float2*)(Xout + (size_t)r1 * HH + col) = v1;
                        }
                    }
                    #pragma unroll
                    for (int v = 0; v < 4; v++) acc[i][j][v] = 0.f;
                }
            }
        }
        __syncthreads();
        stage++; if (stage >= 3) stage = 0;
    }
}

// ---------------- final small GEMM + final aggregation ----------------
__global__ void gemm_small_kernel(const float* __restrict__ X,
                                  const float* __restrict__ W1,
                                  float* __restrict__ S) {
    int row = blockIdx.x * (blockDim.x / 32) + (threadIdx.x >> 5);
    int lane = threadIdx.x & 31;
    if (row >= NN) return;
    float a0 = 0.f, a1 = 0.f, a2 = 0.f;
    const float* xr = X + (size_t)row * HH;
    for (int k = lane; k < HH; k += 32) {
        float xv = xr[k];
        a0 += xv * W1[k * 3 + 0];
        a1 += xv * W1[k * 3 + 1];
        a2 += xv * W1[k * 3 + 2];
    }
    #pragma unroll
    for (int off = 16; off; off >>= 1) {
        a0 += __shfl_down_sync(0xffffffffu, a0, off);
        a1 += __shfl_down_sync(0xffffffffu, a1, off);
        a2 += __shfl_down_sync(0xffffffffu, a2, off);
    }
    if (lane == 0) {
        S[row * 3 + 0] = a0;
        S[row * 3 + 1] = a1;
        S[row * 3 + 2] = a2;
    }
}

__global__ void agg_final_kernel(const float* __restrict__ S,
                                 const float* __restrict__ b1,
                                 float* __restrict__ out) {
    int i = blockIdx.x * blockDim.x + threadIdx.x;
    if (i >= NN) return;
    float a0 = 0.f, a1 = 0.f, a2 = 0.f;
    int beg = g_rowptr[i], end = g_rowptr[i + 1];
    for (int e = beg; e < end; e++) {
        int s = g_col[e];
        float cf = g_coef[e];
        a0 += cf * S[s * 3 + 0];
        a1 += cf * S[s * 3 + 1];
        a2 += cf * S[s * 3 + 2];
    }
    out[i * 3 + 0] = a0 + b1[0];
    out[i * 3 + 1] = a1 + b1[1];
    out[i * 3 + 2] = a2 + b1[2];
}

// ---------------- host orchestration ----------------
extern "C" void kernel_launch(void* const* d_in, const int* in_sizes, int n_in,
                              void* d_out, int out_size) {
    const float* x  = (const float*)d_in[0];
    const void*  ei = d_in[1];
    const float* W0 = (const float*)d_in[2];
    const float* b0 = (const float*)d_in[3];
    const float* Wr = (const float*)d_in[4];
    const float* br = (const float*)d_in[5];
    const float* W1 = (const float*)d_in[6];
    const float* b1 = (const float*)d_in[7];
    float* out  = (float*)d_out;
    float* outX = out + (size_t)NN * CC;

    float* gS;
    __half *gXin, *gXa, *gXb;
    unsigned char *gA, *gW;
    int *gCnt, *gFill;
    unsigned* gIs32;
    cudaGetSymbolAddress((void**)&gXin, g_Xin);
    cudaGetSymbolAddress((void**)&gXa,  g_Xa);
    cudaGetSymbolAddress((void**)&gXb,  g_Xb);
    cudaGetSymbolAddress((void**)&gS,   g_S);
    cudaGetSymbolAddress((void**)&gA,   g_A);
    cudaGetSymbolAddress((void**)&gW,   g_W);
    cudaGetSymbolAddress((void**)&gCnt, g_cnt);
    cudaGetSymbolAddress((void**)&gFill, g_fill);
    cudaGetSymbolAddress((void**)&gIs32, g_is32);

    cudaFuncSetAttribute(gemm_mma_kernel<1>,
                         cudaFuncAttributeMaxDynamicSharedMemorySize, SMEM_REQ);
    cudaFuncSetAttribute(gemm_mma_kernel<0>,
                         cudaFuncAttributeMaxDynamicSharedMemorySize, SMEM_REQ);

    static cudaStream_t sG0 = nullptr, sG1 = nullptr;
    static cudaEvent_t evFork, evX, evW, evEnd0, evEnd1;
    static cudaEvent_t evA[13][4], evGa[13], evGb[13];
    if (!sG0) {
        cudaStreamCreateWithFlags(&sG0, cudaStreamNonBlocking);
        cudaStreamCreateWithFlags(&sG1, cudaStreamNonBlocking);
        cudaEventCreateWithFlags(&evFork, cudaEventDisableTiming);
        cudaEventCreateWithFlags(&evX, cudaEventDisableTiming);
        cudaEventCreateWithFlags(&evW, cudaEventDisableTiming);
        cudaEventCreateWithFlags(&evEnd0, cudaEventDisableTiming);
        cudaEventCreateWithFlags(&evEnd1, cudaEventDisableTiming);
        for (int l = 0; l < 13; l++) {
            cudaEventCreateWithFlags(&evGa[l], cudaEventDisableTiming);
            cudaEventCreateWithFlags(&evGb[l], cudaEventDisableTiming);
            for (int q = 0; q < 4; q++)
                cudaEventCreateWithFlags(&evA[l][q], cudaEventDisableTiming);
        }
    }
    cudaStream_t sA = 0;

    cudaEventRecord(evFork, sA);
    cudaStreamWaitEvent(sG0, evFork, 0);
    cudaStreamWaitEvent(sG1, evFork, 0);

    // sA: CSR chain ; sG0: weight split ; sG1: x convert
    cudaMemsetAsync(gCnt, 0, NN * sizeof(int), sA);
    cudaMemsetAsync(gFill, 0, NN * sizeof(int), sA);
    cudaMemsetAsync(gIs32, 0, sizeof(unsigned), sA);
    detect_kernel<<<148, 256, 0, sA>>>((const uint4*)ei);
    convert_count_kernel<<<(EE + 255) / 256, 256, 0, sA>>>(ei);
    scan_kernel<<<1, 1024, 0, sA>>>();
    fill_kernel<<<(EE + 255) / 256, 256, 0, sA>>>();
    wsplit_kernel<<<dim3(HH, 13), 64, 0, sG0>>>(W0, Wr);
    cudaEventRecord(evW, sG0);
    cudaStreamWaitEvent(sG1, evW, 0);
    xcvt_kernel<<<(NN * FF / 8 + 255) / 256, 256, 0, sG1>>>(x, gXin);
    cudaEventRecord(evX, sG1);
    cudaStreamWaitEvent(sA, evX, 0);

    // M-quarters
    const int qNodeOff[4]  = {0, 12544, 25088, 37632};
    const int qNodeCnt[4]  = {12544, 12544, 12544, 12368};
    const int qTileOff[4]  = {0, 98, 196, 294};
    const int qTilesArr[4] = {98, 98, 98, 97};

    for (int L = 0; L <= 12; L++) {
        int kshift = (L == 0) ? 2 : 3;
        const unsigned char* Wl = gW + (size_t)L * WSLOT;
        const float* bl = (L == 0) ? b0 : (br + (size_t)(L - 1) * HH);
        const __half* Xsrc = (L == 0) ? gXin : ((L & 1) ? gXa : gXb);
        void* Xdst;
        int out16;
        if (L == 12) { Xdst = outX; out16 = 0; }
        else         { Xdst = (L & 1) ? gXb : gXa; out16 = 1; }

        // aggs of this layer need all of last layer's GEMMs
        if (L > 0) {
            cudaStreamWaitEvent(sA, evGa[L - 1], 0);
            cudaStreamWaitEvent(sA, evGb[L - 1], 0);
        }

        for (int q = 0; q < 4; q++) {
            if (L == 0)
                agg16_l0q_kernel<<<(qNodeCnt[q] + 1) / 2, 64, 0, sA>>>(
                    Xsrc, gA, qNodeOff[q], qNodeCnt[q]);
            else
                agg16_q_kernel<<<qNodeCnt[q], 64, 0, sA>>>(
                    Xsrc, gA, qNodeOff[q]);
            cudaEventRecord(evA[L][q], sA);

            cudaStreamWaitEvent(sG0, evA[L][q], 0);
            cudaStreamWaitEvent(sG1, evA[L][q], 0);
            if (out16) {
                gemm_mma_kernel<1><<<qTilesArr[q], 256, SMEM_REQ, sG0>>>(
                    gA, Wl, bl, Xdst, NN, qTilesArr[q], kshift, 0, qTileOff[q]);
                gemm_mma_kernel<1><<<qTilesArr[q], 256, SMEM_REQ, sG1>>>(
                    gA, Wl, bl, Xdst, NN, qTilesArr[q], kshift, 256, qTileOff[q]);
            } else {
                gemm_mma_kernel<0><<<qTilesArr[q], 256, SMEM_REQ, sG0>>>(
                    gA, Wl, bl, Xdst, NN, qTilesArr[q], kshift, 0, qTileOff[q]);
                gemm_mma_kernel<0><<<qTilesArr[q], 256, SMEM_REQ, sG1>>>(
                    gA, Wl, bl, Xdst, NN, qTilesArr[q], kshift, 256, qTileOff[q]);
            }
        }
        cudaEventRecord(evGa[L], sG0);
        cudaEventRecord(evGb[L], sG1);
    }

    // join, then final conv on sA
    cudaEventRecord(evEnd0, sG0);
    cudaEventRecord(evEnd1, sG1);
    cudaStreamWaitEvent(sA, evEnd0, 0);
    cudaStreamWaitEvent(sA, evEnd1, 0);
    gemm_small_kernel<<<(NN + 7) / 8, 256, 0, sA>>>(outX, W1, gS);
    agg_final_kernel<<<(NN + 255) / 256, 256, 0, sA>>>(gS, b1, out);
}

// round 16
// speedup vs baseline: 1.1940x; 1.1940x over previous
#include <cuda_runtime.h>
#include <cuda_fp16.h>
#include <cstdint>

#define NN 50000
#define EE 400000
#define FF 256
#define HH 512
#define CC 3
#define NPAD 50048                        // 391 * 128
#define CHA64 ((size_t)NPAD * 128)        // A k64-chunk stride (bytes)
#define WCH64 ((size_t)512 * 128)         // W k64-chunk stride (bytes)
#define WSLOT ((size_t)8 * 512 * 128)     // W layer slot stride (bytes)
#define ABUF  ((size_t)8 * NPAD * 128)    // one A buffer

// ---------------- device scratch ----------------
__device__ __half g_X16[(size_t)NPAD * HH];              // fp16 activations
__device__ unsigned char g_A[2 * ABUF];                  // fp16 A, double-buffered
__device__ unsigned char g_W[(size_t)13 * 8 * 512 * 128]; // fp16 W, blocked+swizzled
__device__ float g_S[(size_t)NN * CC];
__device__ float g_dinv[NN];
__device__ float g_coef[EE + NN];
__device__ int   g_col[EE + NN];
__device__ int   g_srcA[EE];
__device__ int   g_dstA[EE];
__device__ int   g_cnt[NN];
__device__ int   g_fill[NN];
__device__ int   g_rowptr[NN + 1];
__device__ unsigned g_is32;

// ---------------- preprocessing ----------------
__global__ void detect_kernel(const uint4* __restrict__ w) {
    unsigned local = 0;
    for (int i = blockIdx.x * blockDim.x + threadIdx.x; i < 200000;
         i += gridDim.x * blockDim.x) {
        uint4 v = w[i];
        local |= v.y | v.w;
    }
    #pragma unroll
    for (int off = 16; off; off >>= 1)
        local |= __shfl_xor_sync(0xffffffffu, local, off);
    if ((threadIdx.x & 31) == 0 && local) atomicOr(&g_is32, 1u);
}

__global__ void convert_count_kernel(const void* __restrict__ ei) {
    int e = blockIdx.x * blockDim.x + threadIdx.x;
    if (e >= EE) return;
    int s, d;
    if (g_is32) {
        const int* p = (const int*)ei;
        s = p[e]; d = p[EE + e];
    } else {
        const long long* p = (const long long*)ei;
        s = (int)p[e]; d = (int)p[EE + e];
    }
    g_srcA[e] = s; g_dstA[e] = d;
    atomicAdd(&g_cnt[d], 1);
}

__global__ void scan_kernel() {
    __shared__ int s[1024];
    const int T = 1024;
    int tid = threadIdx.x;
    int chunk = (NN + T - 1) / T;
    int beg = tid * chunk;
    int end = min(beg + chunk, NN);
    int sum = 0;
    for (int i = beg; i < end; i++) sum += g_cnt[i] + 1;
    s[tid] = sum;
    __syncthreads();
    for (int off = 1; off < T; off <<= 1) {
        int v = (tid >= off) ? s[tid - off] : 0;
        __syncthreads();
        s[tid] += v;
        __syncthreads();
    }
    int run = (tid > 0) ? s[tid - 1] : 0;
    for (int i = beg; i < end; i++) {
        int c = g_cnt[i];
        float di = rsqrtf((float)c + 1.0f);
        g_rowptr[i] = run;
        g_dinv[i] = di;
        g_col[run + c] = i;
        g_coef[run + c] = di * di;
        run += c + 1;
    }
    if (tid == T - 1) g_rowptr[NN] = run;
}

__global__ void fill_kernel() {
    int e = blockIdx.x * blockDim.x + threadIdx.x;
    if (e >= EE) return;
    int d = g_dstA[e], s = g_srcA[e];
    int pos = g_rowptr[d] + atomicAdd(&g_fill[d], 1);
    g_col[pos]  = s;
    g_coef[pos] = g_dinv[s] * g_dinv[d];
}

// ---------------- weight: fp16, blocked [L][kc64][n][128B], swizzled -------
__global__ void wsplit_kernel(const float* __restrict__ W0,
                              const float* __restrict__ Wr) {
    int L = blockIdx.y;
    int n = blockIdx.x;
    int K = (L == 0) ? FF : HH;
    const float* W = (L == 0) ? W0 : (Wr + (size_t)(L - 1) * HH * HH);
    unsigned char* slot = g_W + (size_t)L * WSLOT;
    int t = threadIdx.x;
    if (t >= (K >> 3)) return;
    int kc = t >> 3, u = t & 7, k0 = t * 8;
    unsigned w[4];
    #pragma unroll
    for (int p = 0; p < 4; p++) {
        unsigned lo = (unsigned)__half_as_ushort(
            __float2half_rn(W[(size_t)(k0 + 2 * p) * HH + n]));
        unsigned hi = (unsigned)__half_as_ushort(
            __float2half_rn(W[(size_t)(k0 + 2 * p + 1) * HH + n]));
        w[p] = lo | (hi << 16);
    }
    unsigned char* base = slot + (size_t)kc * WCH64 + (size_t)n * 128;
    uint32_t phys = ((uint32_t)(u ^ (n & 7))) << 4;
    *(uint4*)(base + phys) = make_uint4(w[0], w[1], w[2], w[3]);
}

// ---------------- fp32 -> fp16 convert (layer-0 input x) ----------------
__global__ void xcvt_kernel(const float* __restrict__ X, __half* __restrict__ Y) {
    size_t i = (size_t)blockIdx.x * blockDim.x + threadIdx.x;   // 8 floats each
    if (i >= (size_t)NN * FF / 8) return;
    const float4* src = (const float4*)X + 2 * i;
    float4 a = src[0], b = src[1];
    __half2 p0 = __floats2half2_rn(a.x, a.y);
    __half2 p1 = __floats2half2_rn(a.z, a.w);
    __half2 p2 = __floats2half2_rn(b.x, b.y);
    __half2 p3 = __floats2half2_rn(b.z, b.w);
    uint4 o;
    o.x = *(unsigned*)&p0; o.y = *(unsigned*)&p1;
    o.z = *(unsigned*)&p2; o.w = *(unsigned*)&p3;
    ((uint4*)Y)[i] = o;
}

// ---------------- aggregation helpers ----------------
__device__ __forceinline__ void agg_row_body(const uint4* __restrict__ Xv,
                                             int node, size_t colOff,
                                             float* acc) {
    int beg = g_rowptr[node], end = g_rowptr[node + 1];
    int e = beg;
    for (; e + 1 < end; e += 2) {
        int s0 = g_col[e], s1 = g_col[e + 1];
        float c0 = g_coef[e], c1 = g_coef[e + 1];
        uint4 v0 = Xv[(size_t)s0 * 64 + colOff];
        uint4 v1 = Xv[(size_t)s1 * 64 + colOff];
        float2 a0 = __half22float2(*(__half2*)&v0.x);
        float2 a1 = __half22float2(*(__half2*)&v0.y);
        float2 a2 = __half22float2(*(__half2*)&v0.z);
        float2 a3 = __half22float2(*(__half2*)&v0.w);
        acc[0] += c0 * a0.x; acc[1] += c0 * a0.y;
        acc[2] += c0 * a1.x; acc[3] += c0 * a1.y;
        acc[4] += c0 * a2.x; acc[5] += c0 * a2.y;
        acc[6] += c0 * a3.x; acc[7] += c0 * a3.y;
        float2 b0 = __half22float2(*(__half2*)&v1.x);
        float2 b1 = __half22float2(*(__half2*)&v1.y);
        float2 b2 = __half22float2(*(__half2*)&v1.z);
        float2 b3 = __half22float2(*(__half2*)&v1.w);
        acc[0] += c1 * b0.x; acc[1] += c1 * b0.y;
        acc[2] += c1 * b1.x; acc[3] += c1 * b1.y;
        acc[4] += c1 * b2.x; acc[5] += c1 * b2.y;
        acc[6] += c1 * b3.x; acc[7] += c1 * b3.y;
    }
    if (e < end) {
        int s0 = g_col[e];
        float c0 = g_coef[e];
        uint4 v0 = Xv[(size_t)s0 * 64 + colOff];
        float2 a0 = __half22float2(*(__half2*)&v0.x);
        float2 a1 = __half22float2(*(__half2*)&v0.y);
        float2 a2 = __half22float2(*(__half2*)&v0.z);
        float2 a3 = __half22float2(*(__half2*)&v0.w);
        acc[0] += c0 * a0.x; acc[1] += c0 * a0.y;
        acc[2] += c0 * a1.x; acc[3] += c0 * a1.y;
        acc[4] += c0 * a2.x; acc[5] += c0 * a2.y;
        acc[6] += c0 * a3.x; acc[7] += c0 * a3.y;
    }
}

__device__ __forceinline__ void agg_pack_store(unsigned char* __restrict__ gA,
                                               int node, int kc, int u,
                                               const float* acc) {
    uint4 ph;
    __half2 p0 = __floats2half2_rn(acc[0], acc[1]);
    __half2 p1 = __floats2half2_rn(acc[2], acc[3]);
    __half2 p2 = __floats2half2_rn(acc[4], acc[5]);
    __half2 p3 = __floats2half2_rn(acc[6], acc[7]);
    ph.x = *(unsigned*)&p0; ph.y = *(unsigned*)&p1;
    ph.z = *(unsigned*)&p2; ph.w = *(unsigned*)&p3;
    unsigned char* base = gA + (size_t)kc * CHA64 + (size_t)node * 128;
    uint32_t phys = ((uint32_t)(u ^ (node & 7))) << 4;
    *(uint4*)(base + phys) = ph;
}

// layer-0 aggregation (K=256, full): 32 threads/node
__global__ void agg16_l0_kernel(const __half* __restrict__ X,
                                unsigned char* __restrict__ gA) {
    int node = blockIdx.x;
    int t = threadIdx.x;
    const uint4* Xv = (const uint4*)X;
    float acc[8];
    #pragma unroll
    for (int i = 0; i < 8; i++) acc[i] = 0.f;
    int beg = g_rowptr[node], end = g_rowptr[node + 1];
    for (int e = beg; e < end; e++) {
        int s0 = g_col[e];
        float c0 = g_coef[e];
        uint4 v0 = Xv[(size_t)s0 * 32 + t];
        float2 a0 = __half22float2(*(__half2*)&v0.x);
        float2 a1 = __half22float2(*(__half2*)&v0.y);
        float2 a2 = __half22float2(*(__half2*)&v0.z);
        float2 a3 = __half22float2(*(__half2*)&v0.w);
        acc[0] += c0 * a0.x; acc[1] += c0 * a0.y;
        acc[2] += c0 * a1.x; acc[3] += c0 * a1.y;
        acc[4] += c0 * a2.x; acc[5] += c0 * a2.y;
        acc[6] += c0 * a3.x; acc[7] += c0 * a3.y;
    }
    agg_pack_store(gA, node, t >> 3, t & 7, acc);
}

// half-column aggregation (K=512): 2 nodes per 64-thread block
__global__ void agg16_half_kernel(const __half* __restrict__ X,
                                  unsigned char* __restrict__ gA, int half) {
    int node = blockIdx.x * 2 + (threadIdx.x >> 5);
    int t = threadIdx.x & 31;
    if (node >= NN) return;
    const uint4* Xv = (const uint4*)X;
    float acc[8];
    #pragma unroll
    for (int i = 0; i < 8; i++) acc[i] = 0.f;
    agg_row_body(Xv, node, (size_t)(half * 32 + t), acc);
    agg_pack_store(gA, node, half * 4 + (t >> 3), t & 7, acc);
}

// ---------------- persistent HMMA fp16 GEMM, 128x256 tile, TMA, 3-stage ----
#define STG_B   49152
#define SMEM_REQ (1024 + 128 + 3 * STG_B)

#define MMA_F16(cc, A0, A1, A2, A3, B0, B1)                                   \
    asm volatile(                                                             \
        "mma.sync.aligned.m16n8k16.row.col.f32.f16.f16.f32 "                  \
        "{%0,%1,%2,%3}, {%4,%5,%6,%7}, {%8,%9}, {%0,%1,%2,%3};"               \
        : "+f"(cc[0]), "+f"(cc[1]), "+f"(cc[2]), "+f"(cc[3])                  \
        : "r"(A0), "r"(A1), "r"(A2), "r"(A3), "r"(B0), "r"(B1))

#define LDSM4(r0, r1, r2, r3, addr)                                           \
    asm volatile("ldmatrix.sync.aligned.m8n8.x4.shared.b16 {%0,%1,%2,%3}, [%4];" \
        : "=r"(r0), "=r"(r1), "=r"(r2), "=r"(r3) : "r"(addr))

__device__ __forceinline__ void mbar_wait(uint32_t mb, uint32_t parity) {
    uint32_t done;
    asm volatile("{\n\t.reg .pred p;\n\t"
                 "mbarrier.try_wait.parity.shared.b64 p, [%1], %2;\n\t"
                 "selp.b32 %0, 1, 0, p;\n\t}"
                 : "=r"(done) : "r"(mb), "r"(parity) : "memory");
    if (!done) {
        asm volatile("{\n\t.reg .pred P1;\n\t"
                     "WL_%=:\n\t"
                     "mbarrier.try_wait.parity.shared.b64 P1, [%0], %1;\n\t"
                     "@P1 bra.uni WD_%=;\n\t"
                     "bra.uni WL_%=;\n\t"
                     "WD_%=:\n\t}" :: "r"(mb), "r"(parity) : "memory");
    }
}

template <int OUT16>
__global__ void __launch_bounds__(256, 1) gemm_mma_kernel(
    const unsigned char* __restrict__ gA,
    const unsigned char* __restrict__ gW,
    const float* __restrict__ bias, void* __restrict__ XoutV,
    int M, int nTiles, int kshift, int nOff) {
    extern __shared__ char smb[];
    uint32_t sraw;
    asm("{ .reg .u64 t; cvta.to.shared.u64 t, %1; cvt.u32.u64 %0, t; }"
        : "=r"(sraw) : "l"(smb));
    const uint32_t sb = (sraw + 1023) & ~1023u;
    const uint32_t bufBase = sb + 128;

    const int tid = threadIdx.x;
    const int lane = tid & 31, wid = tid >> 5;
    const int g = lane >> 2, t4 = lane & 3;
    const int warpM = wid & 1, warpN = wid >> 1;   // 2M x 4N, warp tile 64x64
    const int kmask = (1 << kshift) - 1;
    const int myTiles = (nTiles - blockIdx.x + gridDim.x - 1) / gridDim.x;
    const int totalSlots = myTiles << kshift;

    const int rx = lane & 7;
    const int aLRow = (lane & 7) + ((lane >> 3) & 1) * 8;
    const int colA = (lane >> 4) & 1;
    const int bLRow = (lane & 7) + ((lane >> 4) & 1) * 8;
    const int colB = (lane >> 3) & 1;
    const uint32_t aRowOff = (uint32_t)(warpM * 64 + aLRow) * 128;
    const uint32_t bRowOff = 16384u + (uint32_t)(warpN * 64 + bLRow) * 128;
    uint32_t pA[4], pB[4];
    #pragma unroll
    for (int j = 0; j < 4; j++) {
        pA[j] = (uint32_t)(((2 * j + colA) ^ rx) << 4);
        pB[j] = (uint32_t)(((2 * j + colB) ^ rx) << 4);
    }

    float acc[4][8][4];
    #pragma unroll
    for (int i = 0; i < 4; i++)
        #pragma unroll
        for (int j = 0; j < 8; j++)
            #pragma unroll
            for (int v = 0; v < 4; v++) acc[i][j][v] = 0.f;

    #define DECODE(s, cc, mB) do {                                             \
        int tI_ = (s) >> kshift;                                               \
        int tile_ = blockIdx.x + tI_ * gridDim.x;                              \
        cc = (s) & kmask;                                                      \
        mB = tile_ << 7;                                                       \
    } while (0)

    #define FILL(stage, cc, mB) do {                                           \
        uint32_t mb_ = sb + (stage) * 8;                                       \
        asm volatile("mbarrier.arrive.expect_tx.shared.b64 _, [%0], %1;"       \
            :: "r"(mb_), "r"(49152u) : "memory");                              \
        uint32_t d_ = bufBase + (stage) * STG_B;                               \
        asm volatile(                                                          \
            "cp.async.bulk.shared::cta.global.mbarrier::complete_tx::bytes "   \
            "[%0], [%1], %2, [%3];"                                            \
            :: "r"(d_), "l"(gA + (size_t)(cc) * CHA64 + (size_t)(mB) * 128),   \
               "r"(16384u), "r"(mb_) : "memory");                              \
        asm volatile(                                                          \
            "cp.async.bulk.shared::cta.global.mbarrier::complete_tx::bytes "   \
            "[%0], [%1], %2, [%3];"                                            \
            :: "r"(d_ + 16384u),                                               \
               "l"(gW + (size_t)(cc) * WCH64 + (size_t)(nOff) * 128),          \
               "r"(32768u), "r"(mb_) : "memory");                              \
    } while (0)

    if (tid == 0) {
        asm volatile("mbarrier.init.shared.b64 [%0], 1;" :: "r"(sb) : "memory");
        asm volatile("mbarrier.init.shared.b64 [%0], 1;" :: "r"(sb + 8) : "memory");
        asm volatile("mbarrier.init.shared.b64 [%0], 1;" :: "r"(sb + 16) : "memory");
    }
    __syncthreads();
    if (tid == 0) {
        int c0, m0; DECODE(0, c0, m0); FILL(0, c0, m0);
        if (totalSlots > 1) { int c1, m1; DECODE(1, c1, m1); FILL(1, c1, m1); }
    }

    int ph[3] = {0, 0, 0};
    int stage = 0;
    for (int s = 0; s < totalSlots; s++) {
        mbar_wait(sb + stage * 8, ph[stage]);
        ph[stage] ^= 1;

        if (tid == 0 && s + 2 < totalSlots) {
            int cN, mN;
            DECODE(s + 2, cN, mN);
            int nst = stage + 2; if (nst >= 3) nst -= 3;
            FILL(nst, cN, mN);
        }

        const uint32_t stA = bufBase + stage * STG_B;
        #pragma unroll
        for (int j = 0; j < 4; j++) {                  // kk16 within k64
            uint32_t bh[8][2];
            #pragma unroll
            for (int jp = 0; jp < 4; jp++) {
                uint32_t ba = stA + bRowOff + jp * 2048u + pB[j];
                LDSM4(bh[2 * jp][0], bh[2 * jp][1],
                      bh[2 * jp + 1][0], bh[2 * jp + 1][1], ba);
            }
            #pragma unroll
            for (int i = 0; i < 4; i++) {
                uint32_t aa = stA + aRowOff + i * 2048u + pA[j];
                uint32_t a0, a1, a2, a3;
                LDSM4(a0, a1, a2, a3, aa);
                #pragma unroll
                for (int jn = 0; jn < 8; jn++)
                    MMA_F16(acc[i][jn], a0, a1, a2, a3, bh[jn][0], bh[jn][1]);
            }
        }

        if ((s & kmask) == kmask) {
            int cE, mB;
            DECODE(s, cE, mB);
            #pragma unroll
            for (int j = 0; j < 8; j++) {
                int col = nOff + warpN * 64 + j * 8 + 2 * t4;
                float bv0 = __ldg(&bias[col]), bv1 = __ldg(&bias[col + 1]);
                #pragma unroll
                for (int i = 0; i < 4; i++) {
                    int r0 = mB + warpM * 64 + i * 16 + g;
                    int r1 = r0 + 8;
                    if (OUT16) {
                        __half* Xout = (__half*)XoutV;
                        if (r0 < M) {
                            __half2 v0 = __floats2half2_rn(
                                fmaxf(acc[i][j][0] + bv0, 0.f),
                                fmaxf(acc[i][j][1] + bv1, 0.f));
                            *(__half2*)(Xout + (size_t)r0 * HH + col) = v0;
                        }
                        if (r1 < M) {
                            __half2 v1 = __floats2half2_rn(
                                fmaxf(acc[i][j][2] + bv0, 0.f),
                                fmaxf(acc[i][j][3] + bv1, 0.f));
                            *(__half2*)(Xout + (size_t)r1 * HH + col) = v1;
                        }
                    } else {
                        float* Xout = (float*)XoutV;
                        if (r0 < M) {
                            float2 v0 = make_float2(fmaxf(acc[i][j][0] + bv0, 0.f),
                                                    fmaxf(acc[i][j][1] + bv1, 0.f));
                            *(float2*)(Xout + (size_t)r0 * HH + col) = v0;
                        }
                        if (r1 < M) {
                            float2 v1 = make_float2(fmaxf(acc[i][j][2] + bv0, 0.f),
                                                    fmaxf(acc[i][j][3] + bv1, 0.f));
                            *(float2*)(Xout + (size_t)r1 * HH + col) = v1;
                        }
                    }
                    #pragma unroll
                    for (int v = 0; v < 4; v++) acc[i][j][v] = 0.f;
                }
            }
        }
        __syncthreads();
        stage++; if (stage >= 3) stage = 0;
    }
}

// ---------------- final small GEMM + final aggregation ----------------
__global__ void gemm_small_kernel(const float* __restrict__ X,
                                  const float* __restrict__ W1,
                                  float* __restrict__ S) {
    int row = blockIdx.x * (blockDim.x / 32) + (threadIdx.x >> 5);
    int lane = threadIdx.x & 31;
    if (row >= NN) return;
    float a0 = 0.f, a1 = 0.f, a2 = 0.f;
    const float* xr = X + (size_t)row * HH;
    for (int k = lane; k < HH; k += 32) {
        float xv = xr[k];
        a0 += xv * W1[k * 3 + 0];
        a1 += xv * W1[k * 3 + 1];
        a2 += xv * W1[k * 3 + 2];
    }
    #pragma unroll
    for (int off = 16; off; off >>= 1) {
        a0 += __shfl_down_sync(0xffffffffu, a0, off);
        a1 += __shfl_down_sync(0xffffffffu, a1, off);
        a2 += __shfl_down_sync(0xffffffffu, a2, off);
    }
    if (lane == 0) {
        S[row * 3 + 0] = a0;
        S[row * 3 + 1] = a1;
        S[row * 3 + 2] = a2;
    }
}

__global__ void agg_final_kernel(const float* __restrict__ S,
                                 const float* __restrict__ b1,
                                 float* __restrict__ out) {
    int i = blockIdx.x * blockDim.x + threadIdx.x;
    if (i >= NN) return;
    float a0 = 0.f, a1 = 0.f, a2 = 0.f;
    int beg = g_rowptr[i], end = g_rowptr[i + 1];
    for (int e = beg; e < end; e++) {
        int s = g_col[e];
        float cf = g_coef[e];
        a0 += cf * S[s * 3 + 0];
        a1 += cf * S[s * 3 + 1];
        a2 += cf * S[s * 3 + 2];
    }
    out[i * 3 + 0] = a0 + b1[0];
    out[i * 3 + 1] = a1 + b1[1];
    out[i * 3 + 2] = a2 + b1[2];
}

// ---------------- host orchestration ----------------
extern "C" void kernel_launch(void* const* d_in, const int* in_sizes, int n_in,
                              void* d_out, int out_size) {
    const float* x  = (const float*)d_in[0];
    const void*  ei = d_in[1];
    const float* W0 = (const float*)d_in[2];
    const float* b0 = (const float*)d_in[3];
    const float* Wr = (const float*)d_in[4];
    const float* br = (const float*)d_in[5];
    const float* W1 = (const float*)d_in[6];
    const float* b1 = (const float*)d_in[7];
    float* out  = (float*)d_out;
    float* outX = out + (size_t)NN * CC;

    float* gS;
    __half* gX16;
    unsigned char *gA, *gW;
    int *gCnt, *gFill;
    unsigned* gIs32;
    cudaGetSymbolAddress((void**)&gX16, g_X16);
    cudaGetSymbolAddress((void**)&gS,  g_S);
    cudaGetSymbolAddress((void**)&gA,  g_A);
    cudaGetSymbolAddress((void**)&gW,  g_W);
    cudaGetSymbolAddress((void**)&gCnt, g_cnt);
    cudaGetSymbolAddress((void**)&gFill, g_fill);
    cudaGetSymbolAddress((void**)&gIs32, g_is32);

    cudaFuncSetAttribute(gemm_mma_kernel<1>,
                         cudaFuncAttributeMaxDynamicSharedMemorySize, SMEM_REQ);
    cudaFuncSetAttribute(gemm_mma_kernel<0>,
                         cudaFuncAttributeMaxDynamicSharedMemorySize, SMEM_REQ);

    static cudaStream_t s1 = nullptr;
    static cudaEvent_t evFork, evX, evW, evG0a, evEnd;
    static cudaEvent_t evA0[13], evA1[13];
    if (!s1) {
        cudaStreamCreateWithFlags(&s1, cudaStreamNonBlocking);
        cudaEventCreateWithFlags(&evFork, cudaEventDisableTiming);
        cudaEventCreateWithFlags(&evX, cudaEventDisableTiming);
        cudaEventCreateWithFlags(&evW, cudaEventDisableTiming);
        cudaEventCreateWithFlags(&evG0a, cudaEventDisableTiming);
        cudaEventCreateWithFlags(&evEnd, cudaEventDisableTiming);
        for (int i = 0; i < 13; i++) {
            cudaEventCreateWithFlags(&evA0[i], cudaEventDisableTiming);
            cudaEventCreateWithFlags(&evA1[i], cudaEventDisableTiming);
        }
    }
    cudaStream_t s0 = 0;

    cudaEventRecord(evFork, s0);
    cudaStreamWaitEvent(s1, evFork, 0);

    // s0: CSR chain ; s1: x convert FIRST (unblocks layer-0 agg), then wsplit
    cudaMemsetAsync(gCnt, 0, NN * sizeof(int), s0);
    cudaMemsetAsync(gFill, 0, NN * sizeof(int), s0);
    cudaMemsetAsync(gIs32, 0, sizeof(unsigned), s0);
    detect_kernel<<<148, 256, 0, s0>>>((const uint4*)ei);
    convert_count_kernel<<<(EE + 255) / 256, 256, 0, s0>>>(ei);
    scan_kernel<<<1, 1024, 0, s0>>>();
    fill_kernel<<<(EE + 255) / 256, 256, 0, s0>>>();
    xcvt_kernel<<<(NN * FF / 8 + 255) / 256, 256, 0, s1>>>(x, gX16);
    cudaEventRecord(evX, s1);
    wsplit_kernel<<<dim3(HH, 13), 64, 0, s1>>>(W0, Wr);
    cudaEventRecord(evW, s1);

    const int gGrid = 148;
    const int nMT = NPAD / 128;   // 391 M-tiles

    // layer 0: full agg (K=256) then two N-half GEMMs (kshift=2)
    cudaStreamWaitEvent(s0, evX, 0);
    agg16_l0_kernel<<<NN, 32, 0, s0>>>(gX16, gA);
    cudaEventRecord(evG0a, s0);
    cudaStreamWaitEvent(s0, evW, 0);     // GEMM needs weights
    cudaStreamWaitEvent(s1, evG0a, 0);   // s1 GEMM needs agg (weights by s1 order)
    gemm_mma_kernel<1><<<gGrid, 256, SMEM_REQ, s0>>>(
        gA, gW, b0, gX16, NN, nMT, 2, 0);
    gemm_mma_kernel<1><<<gGrid, 256, SMEM_REQ, s1>>>(
        gA, gW, b0, gX16, NN, nMT, 2, 256);
    // no cross-join needed: agg half h reads exactly the X columns written by
    // the layer-0 GEMM on stream h (column-stream affinity).

    // layers 1..12: half-column chains on two streams
    for (int L = 1; L <= 12; L++) {
        unsigned char* Abuf = gA + (size_t)(L & 1) * ABUF;
        const unsigned char* Wl = gW + (size_t)L * WSLOT;
        const float* bl = br + (size_t)(L - 1) * HH;

        agg16_half_kernel<<<NN / 2, 64, 0, s0>>>(gX16, Abuf, 0);
        cudaEventRecord(evA0[L], s0);
        agg16_half_kernel<<<NN / 2, 64, 0, s1>>>(gX16, Abuf, 1);
        cudaEventRecord(evA1[L], s1);

        // GEMM halves: each needs BOTH agg halves (K spans all columns)
        cudaStreamWaitEvent(s0, evA1[L], 0);
        cudaStreamWaitEvent(s1, evA0[L], 0);
        if (L == 12) {
            gemm_mma_kernel<0><<<gGrid, 256, SMEM_REQ, s0>>>(
                Abuf, Wl, bl, outX, NN, nMT, 3, 0);
            gemm_mma_kernel<0><<<gGrid, 256, SMEM_REQ, s1>>>(
                Abuf, Wl, bl, outX, NN, nMT, 3, 256);
        } else {
            gemm_mma_kernel<1><<<gGrid, 256, SMEM_REQ, s0>>>(
                Abuf, Wl, bl, gX16, NN, nMT, 3, 0);
            gemm_mma_kernel<1><<<gGrid, 256, SMEM_REQ, s1>>>(
                Abuf, Wl, bl, gX16, NN, nMT, 3, 256);
        }
    }

    // join s1 into s0, then final conv
    cudaEventRecord(evEnd, s1);
    cudaStreamWaitEvent(s0, evEnd, 0);
    gemm_small_kernel<<<(NN + 7) / 8, 256, 0, s0>>>(outX, W1, gS);
    agg_final_kernel<<<(NN + 255) / 256, 256, 0, s0>>>(gS, b1, out);
}